// round 10
// baseline (speedup 1.0000x reference)
#include <cuda_runtime.h>
#include <cuda_bf16.h>
#include <math.h>
#include <stdint.h>

#define SEQ    2048
#define B_SZ   2
#define HIDDEN 3072
#define NHEAD  16
#define NKV    8
#define DHEAD  256
#define QD     (NHEAD * DHEAD)   // 4096
#define KD     (NKV * DHEAD)     // 2048
#define NROW   (B_SZ * SEQ)      // 4096

// ---------------------------------------------------------------------------
// Scratch (allocation-free rule: __device__ globals)
// ---------------------------------------------------------------------------
__device__ __align__(256) float g_Q[(size_t)NROW * QD];
__device__ __align__(256) float g_K[(size_t)NROW * KD];
__device__ __align__(256) float g_V[(size_t)NROW * KD];
__device__ __align__(256) float g_A[(size_t)NROW * QD];

// triple-interleaved split-bf16 operands (K' = 3K) for the projections
__device__ __align__(256) __nv_bfloat16 g_X3 [(size_t)NROW * 3 * HIDDEN];
__device__ __align__(256) __nv_bfloat16 g_Ao3[(size_t)NROW * 3 * QD];
__device__ __align__(256) __nv_bfloat16 g_Wq3[(size_t)QD * 3 * HIDDEN];
__device__ __align__(256) __nv_bfloat16 g_Wk3[(size_t)KD * 3 * HIDDEN];
__device__ __align__(256) __nv_bfloat16 g_Wv3[(size_t)KD * 3 * HIDDEN];
__device__ __align__(256) __nv_bfloat16 g_Wo3[(size_t)HIDDEN * 3 * QD];

// head-major split-bf16 planes for attention: [b][head][s][d]
__device__ __align__(256) __nv_bfloat16 g_Qh[(size_t)NROW * QD];
__device__ __align__(256) __nv_bfloat16 g_Ql[(size_t)NROW * QD];
__device__ __align__(256) __nv_bfloat16 g_Kh[(size_t)NROW * KD];
__device__ __align__(256) __nv_bfloat16 g_Kl[(size_t)NROW * KD];
__device__ __align__(256) __nv_bfloat16 g_Vh[(size_t)NROW * KD];
__device__ __align__(256) __nv_bfloat16 g_Vl[(size_t)NROW * KD];

// ---------------------------------------------------------------------------
// helpers
// ---------------------------------------------------------------------------
__device__ __forceinline__ uint32_t smem_u32(const void* p) {
    uint32_t a;
    asm("{ .reg .u64 t; cvta.to.shared.u64 t, %1; cvt.u32.u64 %0, t; }" : "=r"(a) : "l"(p));
    return a;
}
__device__ __forceinline__ void cp16(uint32_t s, const void* g) {
    asm volatile("cp.async.cg.shared.global [%0], [%1], 16;" :: "r"(s), "l"(g));
}
__device__ __forceinline__ void cp_commit() { asm volatile("cp.async.commit_group;" ::: "memory"); }
template <int N> __device__ __forceinline__ void cp_wait() {
    asm volatile("cp.async.wait_group %0;" :: "n"(N) : "memory");
}
__device__ __forceinline__ void ldsm4(uint32_t* r, uint32_t a) {
    asm volatile("ldmatrix.sync.aligned.m8n8.x4.shared.b16 {%0,%1,%2,%3}, [%4];"
                 : "=r"(r[0]), "=r"(r[1]), "=r"(r[2]), "=r"(r[3]) : "r"(a));
}
__device__ __forceinline__ void ldsm4t(uint32_t* r, uint32_t a) {
    asm volatile("ldmatrix.sync.aligned.m8n8.x4.trans.shared.b16 {%0,%1,%2,%3}, [%4];"
                 : "=r"(r[0]), "=r"(r[1]), "=r"(r[2]), "=r"(r[3]) : "r"(a));
}
__device__ __forceinline__ void mma16816(float* d, const uint32_t* a, uint32_t b0, uint32_t b1) {
    asm volatile(
        "mma.sync.aligned.m16n8k16.row.col.f32.bf16.bf16.f32 "
        "{%0,%1,%2,%3}, {%4,%5,%6,%7}, {%8,%9}, {%0,%1,%2,%3};"
        : "+f"(d[0]), "+f"(d[1]), "+f"(d[2]), "+f"(d[3])
        : "r"(a[0]), "r"(a[1]), "r"(a[2]), "r"(a[3]), "r"(b0), "r"(b1));
}
__device__ __forceinline__ void split1(float x, unsigned short& h, unsigned short& l) {
    __nv_bfloat16 hb = __float2bfloat16(x);
    float r = x - __bfloat162float(hb);
    __nv_bfloat16 lb = __float2bfloat16(r);
    h = *reinterpret_cast<unsigned short*>(&hb);
    l = *reinterpret_cast<unsigned short*>(&lb);
}
__device__ __forceinline__ uint32_t pack_bf16x2(float lo, float hi) {
    uint32_t u;
    asm("cvt.rn.bf16x2.f32 %0, %1, %2;" : "=r"(u) : "f"(hi), "f"(lo));
    return u;
}

// ---------------------------------------------------------------------------
// conversion kernels (projections)
// ---------------------------------------------------------------------------
__global__ __launch_bounds__(256) void conv_split3(
    const float* __restrict__ X, __nv_bfloat16* __restrict__ Y, int n8)
{
    int i = blockIdx.x * 256 + threadIdx.x;
    if (i >= n8) return;
    float4 v0 = ((const float4*)X)[2 * i];
    float4 v1 = ((const float4*)X)[2 * i + 1];
    float e[8] = {v0.x, v0.y, v0.z, v0.w, v1.x, v1.y, v1.z, v1.w};
    union { unsigned short u[24]; uint4 q[3]; } o;
#pragma unroll
    for (int t = 0; t < 8; t++) {
        unsigned short h, l;
        split1(e[t], h, l);
        o.u[3 * t] = h; o.u[3 * t + 1] = h; o.u[3 * t + 2] = l;
    }
    uint4* dst = (uint4*)(Y + (size_t)i * 24);
    dst[0] = o.q[0]; dst[1] = o.q[1]; dst[2] = o.q[2];
}

__global__ __launch_bounds__(256) void conv_trans3(
    const float* __restrict__ W, __nv_bfloat16* __restrict__ W3, int K, int N)
{
    __shared__ float t[32][33];
    const int n0 = blockIdx.x * 32, k0 = blockIdx.y * 32;
    const int tx = threadIdx.x & 31, ty = threadIdx.x >> 5;
    for (int i = ty; i < 32; i += 8)
        t[i][tx] = W[(size_t)(k0 + i) * N + n0 + tx];
    __syncthreads();
    for (int i = ty; i < 32; i += 8) {
        unsigned short h, l;
        split1(t[tx][i], h, l);
        unsigned short* o = (unsigned short*)W3 + (size_t)(n0 + i) * (3 * K) + 3 * (k0 + tx);
        o[0] = h; o[1] = l; o[2] = h;
    }
}

// ---------------------------------------------------------------------------
// bf16 mma.sync GEMM (projections): C = A[M,Kp] @ B^T, B [N,Kp] K-major.
// ---------------------------------------------------------------------------
#define BM 128
#define BN 256
#define BK 64
#define PIPE 3
#define A_BYTES (BM * BK * 2)
#define STAGE_BYTES (A_BYTES + BN * BK * 2)
#define GSMEM (PIPE * STAGE_BYTES)

__global__ __launch_bounds__(256, 1) void gemm_bf16(
    const __nv_bfloat16* __restrict__ A, const __nv_bfloat16* __restrict__ B,
    float* __restrict__ C, int M, int N, int Kp)
{
    extern __shared__ char sm[];
    const uint32_t sb = smem_u32(sm);
    const int tid = threadIdx.x;
    const int wid = tid >> 5, lane = tid & 31;
    const int wm = wid & 1, wn = wid >> 1;
    const int bm = blockIdx.y, bn = blockIdx.x;

    const int arow[4] = {(tid + 0) >> 3, (tid + 256) >> 3, (tid + 512) >> 3, (tid + 768) >> 3};
    const int c16 = tid & 7;
    const uint32_t soff = ((uint32_t)c16 << 4);

    const __nv_bfloat16* Ag = A + (size_t)(bm * BM) * Kp + c16 * 8;
    const __nv_bfloat16* Bg = B + (size_t)(bn * BN) * Kp + c16 * 8;

    const int NC = Kp / BK;

    const int a_r = wm * 64 + (lane & 15);
    const uint32_t a_cb = ((uint32_t)(lane >> 4)) << 4;
    const int b_r = wn * 64 + ((lane >> 4) << 3) + (lane & 7);
    const uint32_t b_cb = ((uint32_t)((lane >> 3) & 1)) << 4;

    float d[4][8][4];
#pragma unroll
    for (int i = 0; i < 4; i++)
#pragma unroll
        for (int j = 0; j < 8; j++)
#pragma unroll
            for (int r = 0; r < 4; r++) d[i][j][r] = 0.f;

    auto issue = [&](int chunk) {
        const int st = chunk % PIPE;
        const uint32_t sA = sb + st * STAGE_BYTES;
        const uint32_t sB = sA + A_BYTES;
        const int k0 = chunk * BK;
#pragma unroll
        for (int j = 0; j < 4; j++) {
            const int row = arow[j];
            uint32_t off = ((uint32_t)row << 7) + soff;
            uint32_t sw = off ^ ((off >> 3) & 0x70);
            cp16(sA + sw, Ag + (size_t)row * Kp + k0);
        }
#pragma unroll
        for (int j = 0; j < 8; j++) {
            const int row = (tid + 256 * j) >> 3;
            uint32_t off = ((uint32_t)row << 7) + soff;
            uint32_t sw = off ^ ((off >> 3) & 0x70);
            cp16(sB + sw, Bg + (size_t)row * Kp + k0);
        }
        cp_commit();
    };

    issue(0);
    issue(1);

    for (int c = 0; c < NC; c++) {
        if (c + 1 < NC) cp_wait<1>(); else cp_wait<0>();
        __syncthreads();
        const int st = c % PIPE;
        const uint32_t sA = sb + st * STAGE_BYTES;
        const uint32_t sB = sA + A_BYTES;
#pragma unroll
        for (int kf = 0; kf < 4; kf++) {
            uint32_t a[4][4], b[4][4];
#pragma unroll
            for (int mf = 0; mf < 4; mf++) {
                uint32_t off = (uint32_t)(a_r + mf * 16) * 128 + kf * 32 + a_cb;
                uint32_t sw = off ^ ((off >> 3) & 0x70);
                ldsm4(a[mf], sA + sw);
            }
#pragma unroll
            for (int nf2 = 0; nf2 < 4; nf2++) {
                uint32_t off = (uint32_t)(b_r + nf2 * 16) * 128 + kf * 32 + b_cb;
                uint32_t sw = off ^ ((off >> 3) & 0x70);
                ldsm4(b[nf2], sB + sw);
            }
#pragma unroll
            for (int mf = 0; mf < 4; mf++)
#pragma unroll
                for (int nf2 = 0; nf2 < 4; nf2++) {
                    mma16816(d[mf][2 * nf2],     a[mf], b[nf2][0], b[nf2][1]);
                    mma16816(d[mf][2 * nf2 + 1], a[mf], b[nf2][2], b[nf2][3]);
                }
        }
        __syncthreads();
        if (c + 2 < NC) issue(c + 2);
    }

    const int rbase = bm * BM + wm * 64 + (lane >> 2);
    const int cbase = bn * BN + wn * 64 + ((lane & 3) << 1);
#pragma unroll
    for (int mf = 0; mf < 4; mf++) {
#pragma unroll
        for (int nf = 0; nf < 8; nf++) {
            const int r0 = rbase + mf * 16;
            const int c0 = cbase + nf * 8;
            *(float2*)(C + (size_t)r0 * N + c0)       = make_float2(d[mf][nf][0], d[mf][nf][1]);
            *(float2*)(C + (size_t)(r0 + 8) * N + c0) = make_float2(d[mf][nf][2], d[mf][nf][3]);
        }
    }
}

// ---------------------------------------------------------------------------
// Fused per-head RMSNorm + RoPE (+ q scale), writing head-major bf16 hi/lo.
// ---------------------------------------------------------------------------
__global__ __launch_bounds__(256) void norm_rope_split(
    const float* __restrict__ cosT, const float* __restrict__ sinT,
    const float* __restrict__ qw, const float* __restrict__ kw)
{
    const int row  = blockIdx.x;
    const int head = blockIdx.y;
    const int d    = threadIdx.x;
    const int b    = row >> 11;
    const int s    = row & (SEQ - 1);

    const float* src;
    const float* w;
    const bool isq = head < NHEAD;
    if (isq) { src = g_Q + (size_t)row * QD + head * DHEAD;           w = qw; }
    else     { src = g_K + (size_t)row * KD + (head - NHEAD) * DHEAD; w = kw; }

    float x = src[d];
    __shared__ float red[8];
    __shared__ float nsh[256];
    float v = x * x;
#pragma unroll
    for (int o = 16; o > 0; o >>= 1) v += __shfl_xor_sync(0xffffffffu, v, o);
    if ((d & 31) == 0) red[d >> 5] = v;
    __syncthreads();
    if (d == 0) {
        float t = 0.f;
#pragma unroll
        for (int i = 0; i < 8; i++) t += red[i];
        red[0] = t;
    }
    __syncthreads();
    const float rms = rsqrtf(red[0] * (1.f / 256.f) + 1e-6f);
    const float n   = x * rms * (1.f + w[d]);
    nsh[d] = n;
    __syncthreads();
    const int i  = d & 127;
    const float c  = cosT[s * 128 + i];
    const float sn = sinT[s * 128 + i];
    float o = (d < 128) ? (n * c - nsh[d + 128] * sn)
                        : (nsh[d - 128] * sn + n * c);
    if (isq) o *= 0.0625f;

    __nv_bfloat16 hb = __float2bfloat16(o);
    __nv_bfloat16 lb = __float2bfloat16(o - __bfloat162float(hb));
    if (isq) {
        const size_t dst = ((size_t)(b * NHEAD + head) * SEQ + s) * DHEAD + d;
        g_Qh[dst] = hb; g_Ql[dst] = lb;
    } else {
        const size_t dst = ((size_t)(b * NKV + head - NHEAD) * SEQ + s) * DHEAD + d;
        g_Kh[dst] = hb; g_Kl[dst] = lb;
    }
}

// V: fp32 [b][s][kv*d] -> bf16 hi/lo planes [b][kv][s][d]
__global__ __launch_bounds__(256) void conv_vsplit(int n)
{
    int i = blockIdx.x * 256 + threadIdx.x;
    if (i >= n) return;
    const int d4  = i & 63;
    const int s   = (i >> 6) & (SEQ - 1);
    const int kvh = (i >> 17) & 7;
    const int b   = i >> 20;
    const float4 v = *(const float4*)(g_V + (size_t)(b * SEQ + s) * KD + kvh * DHEAD + d4 * 4);
    ushort4 h, l;
    split1(v.x, h.x, l.x);
    split1(v.y, h.y, l.y);
    split1(v.z, h.z, l.z);
    split1(v.w, h.w, l.w);
    const size_t dst = ((size_t)(b * NKV + kvh) * SEQ + s) * DHEAD + d4 * 4;
    *(ushort4*)(g_Vh + dst) = h;
    *(ushort4*)(g_Vl + dst) = l;
}

// ---------------------------------------------------------------------------
// Tensor-core flash attention, triple-bf16 split, causal.
// CTA: 128 q-rows x (b,h). 8 warps, each m16 x full d=256. kv-tile = 32.
// ---------------------------------------------------------------------------
#define SQH 0
#define SQL 65536
#define SKH 131072
#define SKL (131072 + 16384)
#define SVH (131072 + 32768)
#define SVL (131072 + 49152)
#define ATT_SMEM (131072 + 65536)   // 196608 bytes

__global__ __launch_bounds__(256, 1) void attn_mma()
{
    extern __shared__ char sm[];
    const uint32_t sb = smem_u32(sm);
    const int tid = threadIdx.x, lane = tid & 31, w = tid >> 5;
    const int qt  = gridDim.x - 1 - blockIdx.x;     // big tiles first
    const int bh  = blockIdx.y;
    const int b = bh >> 4, h = bh & 15, kvh = h >> 1;
    const int q0 = qt * 128;

    const char* Qhg = (const char*)(g_Qh + ((size_t)(b * NHEAD + h) * SEQ + q0) * DHEAD);
    const char* Qlg = (const char*)(g_Ql + ((size_t)(b * NHEAD + h) * SEQ + q0) * DHEAD);
    const char* Khg = (const char*)(g_Kh + (size_t)(b * NKV + kvh) * SEQ * DHEAD);
    const char* Klg = (const char*)(g_Kl + (size_t)(b * NKV + kvh) * SEQ * DHEAD);
    const char* Vhg = (const char*)(g_Vh + (size_t)(b * NKV + kvh) * SEQ * DHEAD);
    const char* Vlg = (const char*)(g_Vl + (size_t)(b * NKV + kvh) * SEQ * DHEAD);

    // Q tile: 128 rows x 32 16B-chunks per plane
#pragma unroll
    for (int i = 0; i < 16; i++) {
        const int id = tid + 256 * i, r = id >> 5, c = id & 31;
        const uint32_t sw = (uint32_t)(r * 512) + (uint32_t)((c ^ (r & 7)) << 4);
        cp16(sb + SQH + sw, Qhg + r * 512 + c * 16);
        cp16(sb + SQL + sw, Qlg + r * 512 + c * 16);
    }
    cp_commit();

    // fragment geometry
    const int a_row   = w * 16 + (lane & 15);
    const int a_coff  = lane >> 4;
    const uint32_t aqh = sb + SQH + a_row * 512;
    const uint32_t aql = sb + SQL + a_row * 512;
    const int kb_row  = (lane & 7) + 8 * (lane >> 4);
    const int kb_coff = (lane >> 3) & 1;
    const int vb_row  = (lane & 7) + 8 * ((lane >> 3) & 1);
    const int vb_coff = lane >> 4;
    const int gr  = lane >> 2;
    const int gc2 = 2 * (lane & 3);

    float acc[32][4];
#pragma unroll
    for (int n = 0; n < 32; n++) {
        acc[n][0] = 0.f; acc[n][1] = 0.f; acc[n][2] = 0.f; acc[n][3] = 0.f;
    }
    float m0 = -INFINITY, m1 = -INFINITY, l0 = 0.f, l1 = 0.f;

    cp_wait<0>();
    __syncthreads();

    const int ntiles = 4 * qt + 4;
    for (int kt = 0; kt < ntiles; kt++) {
        const int k0 = kt * 32;
        __syncthreads();   // previous tile fully consumed
        // K planes (group of 2)
#pragma unroll
        for (int i = 0; i < 4; i++) {
            const int id = tid + 256 * i, r = id >> 5, c = id & 31;
            const uint32_t sw = (uint32_t)(r * 512) + (uint32_t)((c ^ (r & 7)) << 4);
            const size_t go = (size_t)(k0 + r) * 512 + c * 16;
            cp16(sb + SKH + sw, Khg + go);
            cp16(sb + SKL + sw, Klg + go);
        }
        cp_commit();
        // V planes (second group, overlaps QK)
#pragma unroll
        for (int i = 0; i < 4; i++) {
            const int id = tid + 256 * i, r = id >> 5, c = id & 31;
            const uint32_t sw = (uint32_t)(r * 512) + (uint32_t)((c ^ (r & 7)) << 4);
            const size_t go = (size_t)(k0 + r) * 512 + c * 16;
            cp16(sb + SVH + sw, Vhg + go);
            cp16(sb + SVL + sw, Vlg + go);
        }
        cp_commit();
        cp_wait<1>();      // K ready (V may still be in flight)
        __syncthreads();

        // ---- S = Q K^T (triple split) ----
        float s4[4][4];
#pragma unroll
        for (int t = 0; t < 4; t++) { s4[t][0]=0.f; s4[t][1]=0.f; s4[t][2]=0.f; s4[t][3]=0.f; }
#pragma unroll
        for (int k = 0; k < 16; k++) {
            uint32_t ah[4], al[4];
            const uint32_t ca = (uint32_t)(2 * k + a_coff);
            const uint32_t aoff = ((ca ^ (uint32_t)(a_row & 7)) << 4);
            ldsm4(ah, aqh + aoff);
            ldsm4(al, aql + aoff);
#pragma unroll
            for (int p = 0; p < 2; p++) {
                const int row = 16 * p + kb_row;
                const uint32_t ck = (uint32_t)(2 * k + kb_coff);
                const uint32_t koff = (uint32_t)(row * 512) + ((ck ^ (uint32_t)(row & 7)) << 4);
                uint32_t kh4[4], kl4[4];
                ldsm4(kh4, sb + SKH + koff);
                ldsm4(kl4, sb + SKL + koff);
                mma16816(s4[2*p],   ah, kh4[0], kh4[1]);
                mma16816(s4[2*p],   ah, kl4[0], kl4[1]);
                mma16816(s4[2*p],   al, kh4[0], kh4[1]);
                mma16816(s4[2*p+1], ah, kh4[2], kh4[3]);
                mma16816(s4[2*p+1], ah, kl4[2], kl4[3]);
                mma16816(s4[2*p+1], al, kh4[2], kh4[3]);
            }
        }

        // causal mask (only diagonal tiles)
        if (kt >= 4 * qt) {
            const int qrow0 = q0 + w * 16 + gr;
#pragma unroll
            for (int t = 0; t < 4; t++) {
                const int kvc = k0 + 8 * t + gc2;
                if (kvc     > qrow0)     s4[t][0] = -1e9f;
                if (kvc + 1 > qrow0)     s4[t][1] = -1e9f;
                if (kvc     > qrow0 + 8) s4[t][2] = -1e9f;
                if (kvc + 1 > qrow0 + 8) s4[t][3] = -1e9f;
            }
        }

        // ---- online softmax (registers) ----
        float mx0 = -INFINITY, mx1 = -INFINITY;
#pragma unroll
        for (int t = 0; t < 4; t++) {
            mx0 = fmaxf(mx0, fmaxf(s4[t][0], s4[t][1]));
            mx1 = fmaxf(mx1, fmaxf(s4[t][2], s4[t][3]));
        }
        mx0 = fmaxf(mx0, __shfl_xor_sync(0xffffffffu, mx0, 1));
        mx0 = fmaxf(mx0, __shfl_xor_sync(0xffffffffu, mx0, 2));
        mx1 = fmaxf(mx1, __shfl_xor_sync(0xffffffffu, mx1, 1));
        mx1 = fmaxf(mx1, __shfl_xor_sync(0xffffffffu, mx1, 2));
        const float nm0 = fmaxf(m0, mx0), nm1 = fmaxf(m1, mx1);
        const float f0 = __expf(m0 - nm0), f1 = __expf(m1 - nm1);
        m0 = nm0; m1 = nm1;

        float ps0 = 0.f, ps1 = 0.f;
        uint32_t ph[4][2], pl[4][2];
#pragma unroll
        for (int t = 0; t < 4; t++) {
            const float p0 = __expf(s4[t][0] - nm0);
            const float p1 = __expf(s4[t][1] - nm0);
            const float p2 = __expf(s4[t][2] - nm1);
            const float p3 = __expf(s4[t][3] - nm1);
            ps0 += p0 + p1; ps1 += p2 + p3;
            const uint32_t h01 = pack_bf16x2(p0, p1);
            const uint32_t h23 = pack_bf16x2(p2, p3);
            const float r0 = p0 - __uint_as_float(h01 << 16);
            const float r1 = p1 - __uint_as_float(h01 & 0xffff0000u);
            const float r2 = p2 - __uint_as_float(h23 << 16);
            const float r3 = p3 - __uint_as_float(h23 & 0xffff0000u);
            ph[t][0] = h01; ph[t][1] = h23;
            pl[t][0] = pack_bf16x2(r0, r1);
            pl[t][1] = pack_bf16x2(r2, r3);
        }
        ps0 += __shfl_xor_sync(0xffffffffu, ps0, 1);
        ps0 += __shfl_xor_sync(0xffffffffu, ps0, 2);
        ps1 += __shfl_xor_sync(0xffffffffu, ps1, 1);
        ps1 += __shfl_xor_sync(0xffffffffu, ps1, 2);
        l0 = l0 * f0 + ps0;
        l1 = l1 * f1 + ps1;
#pragma unroll
        for (int n = 0; n < 32; n++) {
            acc[n][0] *= f0; acc[n][1] *= f0; acc[n][2] *= f1; acc[n][3] *= f1;
        }

        cp_wait<0>();      // V ready
        __syncthreads();

        // ---- O += P V (triple split, P via c-frag->a-frag trick) ----
#pragma unroll
        for (int j = 0; j < 2; j++) {
            uint32_t ah[4] = {ph[2*j][0], ph[2*j][1], ph[2*j+1][0], ph[2*j+1][1]};
            uint32_t al[4] = {pl[2*j][0], pl[2*j][1], pl[2*j+1][0], pl[2*j+1][1]};
            const int row = 16 * j + vb_row;
            const uint32_t vbase = (uint32_t)(row * 512);
            const uint32_t rx = (uint32_t)(row & 7);
#pragma unroll
            for (int np = 0; np < 16; np++) {
                const uint32_t c = (uint32_t)(2 * np + vb_coff);
                const uint32_t voff = vbase + ((c ^ rx) << 4);
                uint32_t vh4[4], vl4[4];
                ldsm4t(vh4, sb + SVH + voff);
                ldsm4t(vl4, sb + SVL + voff);
                mma16816(acc[2*np],   ah, vh4[0], vh4[1]);
                mma16816(acc[2*np],   ah, vl4[0], vl4[1]);
                mma16816(acc[2*np],   al, vh4[0], vh4[1]);
                mma16816(acc[2*np+1], ah, vh4[2], vh4[3]);
                mma16816(acc[2*np+1], ah, vl4[2], vl4[3]);
                mma16816(acc[2*np+1], al, vh4[2], vh4[3]);
            }
        }
    }

    // epilogue
    const float i0 = 1.f / l0, i1 = 1.f / l1;
    const int r0g = q0 + w * 16 + gr;
    float* O0 = g_A + ((size_t)b * SEQ + r0g) * QD + h * DHEAD + gc2;
    float* O1 = O0 + (size_t)8 * QD;
#pragma unroll
    for (int n = 0; n < 32; n++) {
        *(float2*)(O0 + 8 * n) = make_float2(acc[n][0] * i0, acc[n][1] * i0);
        *(float2*)(O1 + 8 * n) = make_float2(acc[n][2] * i1, acc[n][3] * i1);
    }
}

// ---------------------------------------------------------------------------
extern "C" void kernel_launch(void* const* d_in, const int* in_sizes, int n_in,
                              void* d_out, int out_size)
{
    const float* hidden = (const float*)d_in[0];
    const float* cosT   = (const float*)d_in[1];
    const float* sinT   = (const float*)d_in[2];
    const float* qw     = (const float*)d_in[4];
    const float* kw     = (const float*)d_in[5];
    const float* vw     = (const float*)d_in[6];
    const float* ow     = (const float*)d_in[7];
    const float* qnw    = (const float*)d_in[8];
    const float* knw    = (const float*)d_in[9];
    float* out = (float*)d_out;

    float *Qp, *Kp, *Vp, *Ap;
    __nv_bfloat16 *X3, *Ao3, *Wq3, *Wk3, *Wv3, *Wo3;
    cudaGetSymbolAddress((void**)&Qp, g_Q);
    cudaGetSymbolAddress((void**)&Kp, g_K);
    cudaGetSymbolAddress((void**)&Vp, g_V);
    cudaGetSymbolAddress((void**)&Ap, g_A);
    cudaGetSymbolAddress((void**)&X3, g_X3);
    cudaGetSymbolAddress((void**)&Ao3, g_Ao3);
    cudaGetSymbolAddress((void**)&Wq3, g_Wq3);
    cudaGetSymbolAddress((void**)&Wk3, g_Wk3);
    cudaGetSymbolAddress((void**)&Wv3, g_Wv3);
    cudaGetSymbolAddress((void**)&Wo3, g_Wo3);

    cudaFuncSetAttribute(gemm_bf16, cudaFuncAttributeMaxDynamicSharedMemorySize, GSMEM);
    cudaFuncSetAttribute(attn_mma, cudaFuncAttributeMaxDynamicSharedMemorySize, ATT_SMEM);

    dim3 blk(256);
    // convert activations + weights to triple-interleaved split bf16
    conv_split3<<<(NROW * HIDDEN / 8 + 255) / 256, blk>>>(hidden, X3, NROW * HIDDEN / 8);
    conv_trans3<<<dim3(QD / 32, HIDDEN / 32), blk>>>(qw, Wq3, HIDDEN, QD);
    conv_trans3<<<dim3(KD / 32, HIDDEN / 32), blk>>>(kw, Wk3, HIDDEN, KD);
    conv_trans3<<<dim3(KD / 32, HIDDEN / 32), blk>>>(vw, Wv3, HIDDEN, KD);
    conv_trans3<<<dim3(HIDDEN / 32, QD / 32), blk>>>(ow, Wo3, QD, HIDDEN);

    // QKV projections (tensor cores)
    gemm_bf16<<<dim3(QD / BN, NROW / BM), blk, GSMEM>>>(X3, Wq3, Qp, NROW, QD, 3 * HIDDEN);
    gemm_bf16<<<dim3(KD / BN, NROW / BM), blk, GSMEM>>>(X3, Wk3, Kp, NROW, KD, 3 * HIDDEN);
    gemm_bf16<<<dim3(KD / BN, NROW / BM), blk, GSMEM>>>(X3, Wv3, Vp, NROW, KD, 3 * HIDDEN);

    // RMSNorm + RoPE -> head-major split-bf16 planes; V split
    norm_rope_split<<<dim3(NROW, NHEAD + NKV), blk>>>(cosT, sinT, qnw, knw);
    conv_vsplit<<<(NROW * KD / 4 + 255) / 256, blk>>>(NROW * KD / 4);

    // Tensor-core flash attention
    attn_mma<<<dim3(SEQ / 128, B_SZ * NHEAD), blk, ATT_SMEM>>>();

    // Output projection
    conv_split3<<<(NROW * QD / 8 + 255) / 256, blk>>>(Ap, Ao3, NROW * QD / 8);
    gemm_bf16<<<dim3(HIDDEN / BN, NROW / BM), blk, GSMEM>>>(Ao3, Wo3, out, NROW, HIDDEN, 3 * QD);
}

// round 11
// speedup vs baseline: 1.0013x; 1.0013x over previous
#include <cuda_runtime.h>
#include <cuda_bf16.h>
#include <math.h>
#include <stdint.h>

#define SEQ    2048
#define B_SZ   2
#define HIDDEN 3072
#define NHEAD  16
#define NKV    8
#define DHEAD  256
#define QD     (NHEAD * DHEAD)   // 4096
#define KD     (NKV * DHEAD)     // 2048
#define NROW   (B_SZ * SEQ)      // 4096

// ---------------------------------------------------------------------------
// Scratch (allocation-free rule: __device__ globals)
// ---------------------------------------------------------------------------
__device__ __align__(256) float g_Q[(size_t)NROW * QD];
__device__ __align__(256) float g_K[(size_t)NROW * KD];
__device__ __align__(256) float g_V[(size_t)NROW * KD];
__device__ __align__(256) float g_A[(size_t)NROW * QD];

// triple-interleaved split-bf16 operands (K' = 3K) for the projections
__device__ __align__(256) __nv_bfloat16 g_X3 [(size_t)NROW * 3 * HIDDEN];
__device__ __align__(256) __nv_bfloat16 g_Ao3[(size_t)NROW * 3 * QD];
__device__ __align__(256) __nv_bfloat16 g_Wq3[(size_t)QD * 3 * HIDDEN];
__device__ __align__(256) __nv_bfloat16 g_Wk3[(size_t)KD * 3 * HIDDEN];
__device__ __align__(256) __nv_bfloat16 g_Wv3[(size_t)KD * 3 * HIDDEN];
__device__ __align__(256) __nv_bfloat16 g_Wo3[(size_t)HIDDEN * 3 * QD];

// head-major split-bf16 planes for attention: [b][head][s][d]
__device__ __align__(256) __nv_bfloat16 g_Qh[(size_t)NROW * QD];
__device__ __align__(256) __nv_bfloat16 g_Ql[(size_t)NROW * QD];
__device__ __align__(256) __nv_bfloat16 g_Kh[(size_t)NROW * KD];
__device__ __align__(256) __nv_bfloat16 g_Kl[(size_t)NROW * KD];
__device__ __align__(256) __nv_bfloat16 g_Vh[(size_t)NROW * KD];
__device__ __align__(256) __nv_bfloat16 g_Vl[(size_t)NROW * KD];

// ---------------------------------------------------------------------------
// helpers
// ---------------------------------------------------------------------------
__device__ __forceinline__ uint32_t smem_u32(const void* p) {
    uint32_t a;
    asm("{ .reg .u64 t; cvta.to.shared.u64 t, %1; cvt.u32.u64 %0, t; }" : "=r"(a) : "l"(p));
    return a;
}
__device__ __forceinline__ void cp16(uint32_t s, const void* g) {
    asm volatile("cp.async.cg.shared.global [%0], [%1], 16;" :: "r"(s), "l"(g));
}
__device__ __forceinline__ void cp_commit() { asm volatile("cp.async.commit_group;" ::: "memory"); }
template <int N> __device__ __forceinline__ void cp_wait() {
    asm volatile("cp.async.wait_group %0;" :: "n"(N) : "memory");
}
__device__ __forceinline__ void ldsm4(uint32_t* r, uint32_t a) {
    asm volatile("ldmatrix.sync.aligned.m8n8.x4.shared.b16 {%0,%1,%2,%3}, [%4];"
                 : "=r"(r[0]), "=r"(r[1]), "=r"(r[2]), "=r"(r[3]) : "r"(a));
}
__device__ __forceinline__ void ldsm4t(uint32_t* r, uint32_t a) {
    asm volatile("ldmatrix.sync.aligned.m8n8.x4.trans.shared.b16 {%0,%1,%2,%3}, [%4];"
                 : "=r"(r[0]), "=r"(r[1]), "=r"(r[2]), "=r"(r[3]) : "r"(a));
}
__device__ __forceinline__ void mma16816(float* d, const uint32_t* a, uint32_t b0, uint32_t b1) {
    asm volatile(
        "mma.sync.aligned.m16n8k16.row.col.f32.bf16.bf16.f32 "
        "{%0,%1,%2,%3}, {%4,%5,%6,%7}, {%8,%9}, {%0,%1,%2,%3};"
        : "+f"(d[0]), "+f"(d[1]), "+f"(d[2]), "+f"(d[3])
        : "r"(a[0]), "r"(a[1]), "r"(a[2]), "r"(a[3]), "r"(b0), "r"(b1));
}
__device__ __forceinline__ void split1(float x, unsigned short& h, unsigned short& l) {
    __nv_bfloat16 hb = __float2bfloat16(x);
    float r = x - __bfloat162float(hb);
    __nv_bfloat16 lb = __float2bfloat16(r);
    h = *reinterpret_cast<unsigned short*>(&hb);
    l = *reinterpret_cast<unsigned short*>(&lb);
}
__device__ __forceinline__ uint32_t pack_bf16x2(float lo, float hi) {
    uint32_t u;
    asm("cvt.rn.bf16x2.f32 %0, %1, %2;" : "=r"(u) : "f"(hi), "f"(lo));
    return u;
}

// ---------------------------------------------------------------------------
// conversion kernels (projections)
// ---------------------------------------------------------------------------
__global__ __launch_bounds__(256) void conv_split3(
    const float* __restrict__ X, __nv_bfloat16* __restrict__ Y, int n8)
{
    int i = blockIdx.x * 256 + threadIdx.x;
    if (i >= n8) return;
    float4 v0 = ((const float4*)X)[2 * i];
    float4 v1 = ((const float4*)X)[2 * i + 1];
    float e[8] = {v0.x, v0.y, v0.z, v0.w, v1.x, v1.y, v1.z, v1.w};
    union { unsigned short u[24]; uint4 q[3]; } o;
#pragma unroll
    for (int t = 0; t < 8; t++) {
        unsigned short h, l;
        split1(e[t], h, l);
        o.u[3 * t] = h; o.u[3 * t + 1] = h; o.u[3 * t + 2] = l;
    }
    uint4* dst = (uint4*)(Y + (size_t)i * 24);
    dst[0] = o.q[0]; dst[1] = o.q[1]; dst[2] = o.q[2];
}

__global__ __launch_bounds__(256) void conv_trans3(
    const float* __restrict__ W, __nv_bfloat16* __restrict__ W3, int K, int N)
{
    __shared__ float t[32][33];
    const int n0 = blockIdx.x * 32, k0 = blockIdx.y * 32;
    const int tx = threadIdx.x & 31, ty = threadIdx.x >> 5;
    for (int i = ty; i < 32; i += 8)
        t[i][tx] = W[(size_t)(k0 + i) * N + n0 + tx];
    __syncthreads();
    for (int i = ty; i < 32; i += 8) {
        unsigned short h, l;
        split1(t[tx][i], h, l);
        unsigned short* o = (unsigned short*)W3 + (size_t)(n0 + i) * (3 * K) + 3 * (k0 + tx);
        o[0] = h; o[1] = l; o[2] = h;
    }
}

// ---------------------------------------------------------------------------
// bf16 mma.sync GEMM (projections): C = A[M,Kp] @ B^T, B [N,Kp] K-major.
// ---------------------------------------------------------------------------
#define BM 128
#define BN 256
#define BK 64
#define PIPE 3
#define A_BYTES (BM * BK * 2)
#define STAGE_BYTES (A_BYTES + BN * BK * 2)
#define GSMEM (PIPE * STAGE_BYTES)

__global__ __launch_bounds__(256, 1) void gemm_bf16(
    const __nv_bfloat16* __restrict__ A, const __nv_bfloat16* __restrict__ B,
    float* __restrict__ C, int M, int N, int Kp)
{
    extern __shared__ char sm[];
    const uint32_t sb = smem_u32(sm);
    const int tid = threadIdx.x;
    const int wid = tid >> 5, lane = tid & 31;
    const int wm = wid & 1, wn = wid >> 1;
    const int bm = blockIdx.y, bn = blockIdx.x;

    const int arow[4] = {(tid + 0) >> 3, (tid + 256) >> 3, (tid + 512) >> 3, (tid + 768) >> 3};
    const int c16 = tid & 7;
    const uint32_t soff = ((uint32_t)c16 << 4);

    const __nv_bfloat16* Ag = A + (size_t)(bm * BM) * Kp + c16 * 8;
    const __nv_bfloat16* Bg = B + (size_t)(bn * BN) * Kp + c16 * 8;

    const int NC = Kp / BK;

    const int a_r = wm * 64 + (lane & 15);
    const uint32_t a_cb = ((uint32_t)(lane >> 4)) << 4;
    const int b_r = wn * 64 + ((lane >> 4) << 3) + (lane & 7);
    const uint32_t b_cb = ((uint32_t)((lane >> 3) & 1)) << 4;

    float d[4][8][4];
#pragma unroll
    for (int i = 0; i < 4; i++)
#pragma unroll
        for (int j = 0; j < 8; j++)
#pragma unroll
            for (int r = 0; r < 4; r++) d[i][j][r] = 0.f;

    auto issue = [&](int chunk) {
        const int st = chunk % PIPE;
        const uint32_t sA = sb + st * STAGE_BYTES;
        const uint32_t sB = sA + A_BYTES;
        const int k0 = chunk * BK;
#pragma unroll
        for (int j = 0; j < 4; j++) {
            const int row = arow[j];
            uint32_t off = ((uint32_t)row << 7) + soff;
            uint32_t sw = off ^ ((off >> 3) & 0x70);
            cp16(sA + sw, Ag + (size_t)row * Kp + k0);
        }
#pragma unroll
        for (int j = 0; j < 8; j++) {
            const int row = (tid + 256 * j) >> 3;
            uint32_t off = ((uint32_t)row << 7) + soff;
            uint32_t sw = off ^ ((off >> 3) & 0x70);
            cp16(sB + sw, Bg + (size_t)row * Kp + k0);
        }
        cp_commit();
    };

    issue(0);
    issue(1);

    for (int c = 0; c < NC; c++) {
        if (c + 1 < NC) cp_wait<1>(); else cp_wait<0>();
        __syncthreads();
        const int st = c % PIPE;
        const uint32_t sA = sb + st * STAGE_BYTES;
        const uint32_t sB = sA + A_BYTES;
#pragma unroll
        for (int kf = 0; kf < 4; kf++) {
            uint32_t a[4][4], b[4][4];
#pragma unroll
            for (int mf = 0; mf < 4; mf++) {
                uint32_t off = (uint32_t)(a_r + mf * 16) * 128 + kf * 32 + a_cb;
                uint32_t sw = off ^ ((off >> 3) & 0x70);
                ldsm4(a[mf], sA + sw);
            }
#pragma unroll
            for (int nf2 = 0; nf2 < 4; nf2++) {
                uint32_t off = (uint32_t)(b_r + nf2 * 16) * 128 + kf * 32 + b_cb;
                uint32_t sw = off ^ ((off >> 3) & 0x70);
                ldsm4(b[nf2], sB + sw);
            }
#pragma unroll
            for (int mf = 0; mf < 4; mf++)
#pragma unroll
                for (int nf2 = 0; nf2 < 4; nf2++) {
                    mma16816(d[mf][2 * nf2],     a[mf], b[nf2][0], b[nf2][1]);
                    mma16816(d[mf][2 * nf2 + 1], a[mf], b[nf2][2], b[nf2][3]);
                }
        }
        __syncthreads();
        if (c + 2 < NC) issue(c + 2);
    }

    const int rbase = bm * BM + wm * 64 + (lane >> 2);
    const int cbase = bn * BN + wn * 64 + ((lane & 3) << 1);
#pragma unroll
    for (int mf = 0; mf < 4; mf++) {
#pragma unroll
        for (int nf = 0; nf < 8; nf++) {
            const int r0 = rbase + mf * 16;
            const int c0 = cbase + nf * 8;
            *(float2*)(C + (size_t)r0 * N + c0)       = make_float2(d[mf][nf][0], d[mf][nf][1]);
            *(float2*)(C + (size_t)(r0 + 8) * N + c0) = make_float2(d[mf][nf][2], d[mf][nf][3]);
        }
    }
}

// ---------------------------------------------------------------------------
// Fused per-head RMSNorm + RoPE (+ q scale), writing head-major bf16 hi/lo.
// ---------------------------------------------------------------------------
__global__ __launch_bounds__(256) void norm_rope_split(
    const float* __restrict__ cosT, const float* __restrict__ sinT,
    const float* __restrict__ qw, const float* __restrict__ kw)
{
    const int row  = blockIdx.x;
    const int head = blockIdx.y;
    const int d    = threadIdx.x;
    const int b    = row >> 11;
    const int s    = row & (SEQ - 1);

    const float* src;
    const float* w;
    const bool isq = head < NHEAD;
    if (isq) { src = g_Q + (size_t)row * QD + head * DHEAD;           w = qw; }
    else     { src = g_K + (size_t)row * KD + (head - NHEAD) * DHEAD; w = kw; }

    float x = src[d];
    __shared__ float red[8];
    __shared__ float nsh[256];
    float v = x * x;
#pragma unroll
    for (int o = 16; o > 0; o >>= 1) v += __shfl_xor_sync(0xffffffffu, v, o);
    if ((d & 31) == 0) red[d >> 5] = v;
    __syncthreads();
    if (d == 0) {
        float t = 0.f;
#pragma unroll
        for (int i = 0; i < 8; i++) t += red[i];
        red[0] = t;
    }
    __syncthreads();
    const float rms = rsqrtf(red[0] * (1.f / 256.f) + 1e-6f);
    const float n   = x * rms * (1.f + w[d]);
    nsh[d] = n;
    __syncthreads();
    const int i  = d & 127;
    const float c  = cosT[s * 128 + i];
    const float sn = sinT[s * 128 + i];
    float o = (d < 128) ? (n * c - nsh[d + 128] * sn)
                        : (nsh[d - 128] * sn + n * c);
    if (isq) o *= 0.0625f;

    __nv_bfloat16 hb = __float2bfloat16(o);
    __nv_bfloat16 lb = __float2bfloat16(o - __bfloat162float(hb));
    if (isq) {
        const size_t dst = ((size_t)(b * NHEAD + head) * SEQ + s) * DHEAD + d;
        g_Qh[dst] = hb; g_Ql[dst] = lb;
    } else {
        const size_t dst = ((size_t)(b * NKV + head - NHEAD) * SEQ + s) * DHEAD + d;
        g_Kh[dst] = hb; g_Kl[dst] = lb;
    }
}

// V: fp32 [b][s][kv*d] -> bf16 hi/lo planes [b][kv][s][d]
__global__ __launch_bounds__(256) void conv_vsplit(int n)
{
    int i = blockIdx.x * 256 + threadIdx.x;
    if (i >= n) return;
    const int d4  = i & 63;
    const int s   = (i >> 6) & (SEQ - 1);
    const int kvh = (i >> 17) & 7;
    const int b   = i >> 20;
    const float4 v = *(const float4*)(g_V + (size_t)(b * SEQ + s) * KD + kvh * DHEAD + d4 * 4);
    ushort4 h, l;
    split1(v.x, h.x, l.x);
    split1(v.y, h.y, l.y);
    split1(v.z, h.z, l.z);
    split1(v.w, h.w, l.w);
    const size_t dst = ((size_t)(b * NKV + kvh) * SEQ + s) * DHEAD + d4 * 4;
    *(ushort4*)(g_Vh + dst) = h;
    *(ushort4*)(g_Vl + dst) = l;
}

// ---------------------------------------------------------------------------
// Tensor-core flash attention, triple-bf16 split, causal.
// CTA: 128 q-rows x (b,h). 8 warps, each m16 x full d=256. kv-tile = 32.
// ---------------------------------------------------------------------------
#define SQH 0
#define SQL 65536
#define SKH 131072
#define SKL (131072 + 16384)
#define SVH (131072 + 32768)
#define SVL (131072 + 49152)
#define ATT_SMEM (131072 + 65536)   // 196608 bytes

__global__ __launch_bounds__(256, 1) void attn_mma()
{
    extern __shared__ char sm[];
    const uint32_t sb = smem_u32(sm);
    const int tid = threadIdx.x, lane = tid & 31, w = tid >> 5;
    const int qt  = gridDim.x - 1 - blockIdx.x;     // big tiles first
    const int bh  = blockIdx.y;
    const int b = bh >> 4, h = bh & 15, kvh = h >> 1;
    const int q0 = qt * 128;

    const char* Qhg = (const char*)(g_Qh + ((size_t)(b * NHEAD + h) * SEQ + q0) * DHEAD);
    const char* Qlg = (const char*)(g_Ql + ((size_t)(b * NHEAD + h) * SEQ + q0) * DHEAD);
    const char* Khg = (const char*)(g_Kh + (size_t)(b * NKV + kvh) * SEQ * DHEAD);
    const char* Klg = (const char*)(g_Kl + (size_t)(b * NKV + kvh) * SEQ * DHEAD);
    const char* Vhg = (const char*)(g_Vh + (size_t)(b * NKV + kvh) * SEQ * DHEAD);
    const char* Vlg = (const char*)(g_Vl + (size_t)(b * NKV + kvh) * SEQ * DHEAD);

    // Q tile: 128 rows x 32 16B-chunks per plane
#pragma unroll
    for (int i = 0; i < 16; i++) {
        const int id = tid + 256 * i, r = id >> 5, c = id & 31;
        const uint32_t sw = (uint32_t)(r * 512) + (uint32_t)((c ^ (r & 7)) << 4);
        cp16(sb + SQH + sw, Qhg + r * 512 + c * 16);
        cp16(sb + SQL + sw, Qlg + r * 512 + c * 16);
    }
    cp_commit();

    // fragment geometry
    const int a_row   = w * 16 + (lane & 15);
    const int a_coff  = lane >> 4;
    const uint32_t aqh = sb + SQH + a_row * 512;
    const uint32_t aql = sb + SQL + a_row * 512;
    const int kb_row  = (lane & 7) + 8 * (lane >> 4);
    const int kb_coff = (lane >> 3) & 1;
    const int vb_row  = (lane & 7) + 8 * ((lane >> 3) & 1);
    const int vb_coff = lane >> 4;
    const int gr  = lane >> 2;
    const int gc2 = 2 * (lane & 3);

    float acc[32][4];
#pragma unroll
    for (int n = 0; n < 32; n++) {
        acc[n][0] = 0.f; acc[n][1] = 0.f; acc[n][2] = 0.f; acc[n][3] = 0.f;
    }
    float m0 = -INFINITY, m1 = -INFINITY, l0 = 0.f, l1 = 0.f;

    cp_wait<0>();
    __syncthreads();

    const int ntiles = 4 * qt + 4;
    for (int kt = 0; kt < ntiles; kt++) {
        const int k0 = kt * 32;
        __syncthreads();   // previous tile fully consumed
        // K planes (group of 2)
#pragma unroll
        for (int i = 0; i < 4; i++) {
            const int id = tid + 256 * i, r = id >> 5, c = id & 31;
            const uint32_t sw = (uint32_t)(r * 512) + (uint32_t)((c ^ (r & 7)) << 4);
            const size_t go = (size_t)(k0 + r) * 512 + c * 16;
            cp16(sb + SKH + sw, Khg + go);
            cp16(sb + SKL + sw, Klg + go);
        }
        cp_commit();
        // V planes (second group, overlaps QK)
#pragma unroll
        for (int i = 0; i < 4; i++) {
            const int id = tid + 256 * i, r = id >> 5, c = id & 31;
            const uint32_t sw = (uint32_t)(r * 512) + (uint32_t)((c ^ (r & 7)) << 4);
            const size_t go = (size_t)(k0 + r) * 512 + c * 16;
            cp16(sb + SVH + sw, Vhg + go);
            cp16(sb + SVL + sw, Vlg + go);
        }
        cp_commit();
        cp_wait<1>();      // K ready (V may still be in flight)
        __syncthreads();

        // ---- S = Q K^T (triple split) ----
        float s4[4][4];
#pragma unroll
        for (int t = 0; t < 4; t++) { s4[t][0]=0.f; s4[t][1]=0.f; s4[t][2]=0.f; s4[t][3]=0.f; }
#pragma unroll
        for (int k = 0; k < 16; k++) {
            uint32_t ah[4], al[4];
            const uint32_t ca = (uint32_t)(2 * k + a_coff);
            const uint32_t aoff = ((ca ^ (uint32_t)(a_row & 7)) << 4);
            ldsm4(ah, aqh + aoff);
            ldsm4(al, aql + aoff);
#pragma unroll
            for (int p = 0; p < 2; p++) {
                const int row = 16 * p + kb_row;
                const uint32_t ck = (uint32_t)(2 * k + kb_coff);
                const uint32_t koff = (uint32_t)(row * 512) + ((ck ^ (uint32_t)(row & 7)) << 4);
                uint32_t kh4[4], kl4[4];
                ldsm4(kh4, sb + SKH + koff);
                ldsm4(kl4, sb + SKL + koff);
                mma16816(s4[2*p],   ah, kh4[0], kh4[1]);
                mma16816(s4[2*p],   ah, kl4[0], kl4[1]);
                mma16816(s4[2*p],   al, kh4[0], kh4[1]);
                mma16816(s4[2*p+1], ah, kh4[2], kh4[3]);
                mma16816(s4[2*p+1], ah, kl4[2], kl4[3]);
                mma16816(s4[2*p+1], al, kh4[2], kh4[3]);
            }
        }

        // causal mask (only diagonal tiles)
        if (kt >= 4 * qt) {
            const int qrow0 = q0 + w * 16 + gr;
#pragma unroll
            for (int t = 0; t < 4; t++) {
                const int kvc = k0 + 8 * t + gc2;
                if (kvc     > qrow0)     s4[t][0] = -1e9f;
                if (kvc + 1 > qrow0)     s4[t][1] = -1e9f;
                if (kvc     > qrow0 + 8) s4[t][2] = -1e9f;
                if (kvc + 1 > qrow0 + 8) s4[t][3] = -1e9f;
            }
        }

        // ---- online softmax (registers) ----
        float mx0 = -INFINITY, mx1 = -INFINITY;
#pragma unroll
        for (int t = 0; t < 4; t++) {
            mx0 = fmaxf(mx0, fmaxf(s4[t][0], s4[t][1]));
            mx1 = fmaxf(mx1, fmaxf(s4[t][2], s4[t][3]));
        }
        mx0 = fmaxf(mx0, __shfl_xor_sync(0xffffffffu, mx0, 1));
        mx0 = fmaxf(mx0, __shfl_xor_sync(0xffffffffu, mx0, 2));
        mx1 = fmaxf(mx1, __shfl_xor_sync(0xffffffffu, mx1, 1));
        mx1 = fmaxf(mx1, __shfl_xor_sync(0xffffffffu, mx1, 2));
        const float nm0 = fmaxf(m0, mx0), nm1 = fmaxf(m1, mx1);
        const float f0 = __expf(m0 - nm0), f1 = __expf(m1 - nm1);
        m0 = nm0; m1 = nm1;

        float ps0 = 0.f, ps1 = 0.f;
        uint32_t ph[4][2], pl[4][2];
#pragma unroll
        for (int t = 0; t < 4; t++) {
            const float p0 = __expf(s4[t][0] - nm0);
            const float p1 = __expf(s4[t][1] - nm0);
            const float p2 = __expf(s4[t][2] - nm1);
            const float p3 = __expf(s4[t][3] - nm1);
            ps0 += p0 + p1; ps1 += p2 + p3;
            const uint32_t h01 = pack_bf16x2(p0, p1);
            const uint32_t h23 = pack_bf16x2(p2, p3);
            const float r0 = p0 - __uint_as_float(h01 << 16);
            const float r1 = p1 - __uint_as_float(h01 & 0xffff0000u);
            const float r2 = p2 - __uint_as_float(h23 << 16);
            const float r3 = p3 - __uint_as_float(h23 & 0xffff0000u);
            ph[t][0] = h01; ph[t][1] = h23;
            pl[t][0] = pack_bf16x2(r0, r1);
            pl[t][1] = pack_bf16x2(r2, r3);
        }
        ps0 += __shfl_xor_sync(0xffffffffu, ps0, 1);
        ps0 += __shfl_xor_sync(0xffffffffu, ps0, 2);
        ps1 += __shfl_xor_sync(0xffffffffu, ps1, 1);
        ps1 += __shfl_xor_sync(0xffffffffu, ps1, 2);
        l0 = l0 * f0 + ps0;
        l1 = l1 * f1 + ps1;
#pragma unroll
        for (int n = 0; n < 32; n++) {
            acc[n][0] *= f0; acc[n][1] *= f0; acc[n][2] *= f1; acc[n][3] *= f1;
        }

        cp_wait<0>();      // V ready
        __syncthreads();

        // ---- O += P V (triple split, P via c-frag->a-frag trick) ----
#pragma unroll
        for (int j = 0; j < 2; j++) {
            uint32_t ah[4] = {ph[2*j][0], ph[2*j][1], ph[2*j+1][0], ph[2*j+1][1]};
            uint32_t al[4] = {pl[2*j][0], pl[2*j][1], pl[2*j+1][0], pl[2*j+1][1]};
            const int row = 16 * j + vb_row;
            const uint32_t vbase = (uint32_t)(row * 512);
            const uint32_t rx = (uint32_t)(row & 7);
#pragma unroll
            for (int np = 0; np < 16; np++) {
                const uint32_t c = (uint32_t)(2 * np + vb_coff);
                const uint32_t voff = vbase + ((c ^ rx) << 4);
                uint32_t vh4[4], vl4[4];
                ldsm4t(vh4, sb + SVH + voff);
                ldsm4t(vl4, sb + SVL + voff);
                mma16816(acc[2*np],   ah, vh4[0], vh4[1]);
                mma16816(acc[2*np],   ah, vl4[0], vl4[1]);
                mma16816(acc[2*np],   al, vh4[0], vh4[1]);
                mma16816(acc[2*np+1], ah, vh4[2], vh4[3]);
                mma16816(acc[2*np+1], ah, vl4[2], vl4[3]);
                mma16816(acc[2*np+1], al, vh4[2], vh4[3]);
            }
        }
    }

    // epilogue
    const float i0 = 1.f / l0, i1 = 1.f / l1;
    const int r0g = q0 + w * 16 + gr;
    float* O0 = g_A + ((size_t)b * SEQ + r0g) * QD + h * DHEAD + gc2;
    float* O1 = O0 + (size_t)8 * QD;
#pragma unroll
    for (int n = 0; n < 32; n++) {
        *(float2*)(O0 + 8 * n) = make_float2(acc[n][0] * i0, acc[n][1] * i0);
        *(float2*)(O1 + 8 * n) = make_float2(acc[n][2] * i1, acc[n][3] * i1);
    }
}

// ---------------------------------------------------------------------------
extern "C" void kernel_launch(void* const* d_in, const int* in_sizes, int n_in,
                              void* d_out, int out_size)
{
    const float* hidden = (const float*)d_in[0];
    const float* cosT   = (const float*)d_in[1];
    const float* sinT   = (const float*)d_in[2];
    const float* qw     = (const float*)d_in[4];
    const float* kw     = (const float*)d_in[5];
    const float* vw     = (const float*)d_in[6];
    const float* ow     = (const float*)d_in[7];
    const float* qnw    = (const float*)d_in[8];
    const float* knw    = (const float*)d_in[9];
    float* out = (float*)d_out;

    float *Qp, *Kp, *Vp, *Ap;
    __nv_bfloat16 *X3, *Ao3, *Wq3, *Wk3, *Wv3, *Wo3;
    cudaGetSymbolAddress((void**)&Qp, g_Q);
    cudaGetSymbolAddress((void**)&Kp, g_K);
    cudaGetSymbolAddress((void**)&Vp, g_V);
    cudaGetSymbolAddress((void**)&Ap, g_A);
    cudaGetSymbolAddress((void**)&X3, g_X3);
    cudaGetSymbolAddress((void**)&Ao3, g_Ao3);
    cudaGetSymbolAddress((void**)&Wq3, g_Wq3);
    cudaGetSymbolAddress((void**)&Wk3, g_Wk3);
    cudaGetSymbolAddress((void**)&Wv3, g_Wv3);
    cudaGetSymbolAddress((void**)&Wo3, g_Wo3);

    cudaFuncSetAttribute(gemm_bf16, cudaFuncAttributeMaxDynamicSharedMemorySize, GSMEM);
    cudaFuncSetAttribute(attn_mma, cudaFuncAttributeMaxDynamicSharedMemorySize, ATT_SMEM);

    dim3 blk(256);
    // convert activations + weights to triple-interleaved split bf16
    conv_split3<<<(NROW * HIDDEN / 8 + 255) / 256, blk>>>(hidden, X3, NROW * HIDDEN / 8);
    conv_trans3<<<dim3(QD / 32, HIDDEN / 32), blk>>>(qw, Wq3, HIDDEN, QD);
    conv_trans3<<<dim3(KD / 32, HIDDEN / 32), blk>>>(kw, Wk3, HIDDEN, KD);
    conv_trans3<<<dim3(KD / 32, HIDDEN / 32), blk>>>(vw, Wv3, HIDDEN, KD);
    conv_trans3<<<dim3(HIDDEN / 32, QD / 32), blk>>>(ow, Wo3, QD, HIDDEN);

    // QKV projections (tensor cores)
    gemm_bf16<<<dim3(QD / BN, NROW / BM), blk, GSMEM>>>(X3, Wq3, Qp, NROW, QD, 3 * HIDDEN);
    gemm_bf16<<<dim3(KD / BN, NROW / BM), blk, GSMEM>>>(X3, Wk3, Kp, NROW, KD, 3 * HIDDEN);
    gemm_bf16<<<dim3(KD / BN, NROW / BM), blk, GSMEM>>>(X3, Wv3, Vp, NROW, KD, 3 * HIDDEN);

    // RMSNorm + RoPE -> head-major split-bf16 planes; V split
    norm_rope_split<<<dim3(NROW, NHEAD + NKV), blk>>>(cosT, sinT, qnw, knw);
    conv_vsplit<<<(NROW * KD / 4 + 255) / 256, blk>>>(NROW * KD / 4);

    // Tensor-core flash attention
    attn_mma<<<dim3(SEQ / 128, B_SZ * NHEAD), blk, ATT_SMEM>>>();

    // Output projection
    conv_split3<<<(NROW * QD / 8 + 255) / 256, blk>>>(Ap, Ao3, NROW * QD / 8);
    gemm_bf16<<<dim3(HIDDEN / BN, NROW / BM), blk, GSMEM>>>(Ao3, Wo3, out, NROW, HIDDEN, 3 * QD);
}

// round 15
// speedup vs baseline: 1.0535x; 1.0521x over previous
#include <cuda_runtime.h>
#include <cuda_bf16.h>
#include <math.h>
#include <stdint.h>

#define SEQ    2048
#define B_SZ   2
#define HIDDEN 3072
#define NHEAD  16
#define NKV    8
#define DHEAD  256
#define QD     (NHEAD * DHEAD)   // 4096
#define KD     (NKV * DHEAD)     // 2048
#define NROW   (B_SZ * SEQ)      // 4096
#define NQK    (QD + KD)         // 6144 (fp32 QK buffer width)

// ---------------------------------------------------------------------------
// Scratch (allocation-free rule: __device__ globals)
// ---------------------------------------------------------------------------
__device__ __align__(256) float g_QKV[(size_t)NROW * NQK];     // Q|K fp32 (pre-norm)

// triple-interleaved split-bf16 operands (K' = 3K) for the projections
__device__ __align__(256) __nv_bfloat16 g_X3 [(size_t)NROW * 3 * HIDDEN];
__device__ __align__(256) __nv_bfloat16 g_Ao3[(size_t)NROW * 3 * QD];
__device__ __align__(256) __nv_bfloat16 g_Wq3[(size_t)QD * 3 * HIDDEN];
__device__ __align__(256) __nv_bfloat16 g_Wk3[(size_t)KD * 3 * HIDDEN];
__device__ __align__(256) __nv_bfloat16 g_Wv3[(size_t)KD * 3 * HIDDEN];
__device__ __align__(256) __nv_bfloat16 g_Wo3[(size_t)HIDDEN * 3 * QD];

// head-major split-bf16 planes for attention: [b][head][s][d]
__device__ __align__(256) __nv_bfloat16 g_Qh[(size_t)NROW * QD];
__device__ __align__(256) __nv_bfloat16 g_Ql[(size_t)NROW * QD];
__device__ __align__(256) __nv_bfloat16 g_Kh[(size_t)NROW * KD];
__device__ __align__(256) __nv_bfloat16 g_Kl[(size_t)NROW * KD];
__device__ __align__(256) __nv_bfloat16 g_Vh[(size_t)NROW * KD];
__device__ __align__(256) __nv_bfloat16 g_Vl[(size_t)NROW * KD];

// ---------------------------------------------------------------------------
// helpers
// ---------------------------------------------------------------------------
__device__ __forceinline__ uint32_t smem_u32(const void* p) {
    uint32_t a;
    asm("{ .reg .u64 t; cvta.to.shared.u64 t, %1; cvt.u32.u64 %0, t; }" : "=r"(a) : "l"(p));
    return a;
}
__device__ __forceinline__ void cp16(uint32_t s, const void* g) {
    asm volatile("cp.async.cg.shared.global [%0], [%1], 16;" :: "r"(s), "l"(g));
}
__device__ __forceinline__ void cp_commit() { asm volatile("cp.async.commit_group;" ::: "memory"); }
template <int N> __device__ __forceinline__ void cp_wait() {
    asm volatile("cp.async.wait_group %0;" :: "n"(N) : "memory");
}
__device__ __forceinline__ void ldsm4(uint32_t* r, uint32_t a) {
    asm volatile("ldmatrix.sync.aligned.m8n8.x4.shared.b16 {%0,%1,%2,%3}, [%4];"
                 : "=r"(r[0]), "=r"(r[1]), "=r"(r[2]), "=r"(r[3]) : "r"(a));
}
__device__ __forceinline__ void ldsm4t(uint32_t* r, uint32_t a) {
    asm volatile("ldmatrix.sync.aligned.m8n8.x4.trans.shared.b16 {%0,%1,%2,%3}, [%4];"
                 : "=r"(r[0]), "=r"(r[1]), "=r"(r[2]), "=r"(r[3]) : "r"(a));
}
__device__ __forceinline__ void mma16816(float* d, const uint32_t* a, uint32_t b0, uint32_t b1) {
    asm volatile(
        "mma.sync.aligned.m16n8k16.row.col.f32.bf16.bf16.f32 "
        "{%0,%1,%2,%3}, {%4,%5,%6,%7}, {%8,%9}, {%0,%1,%2,%3};"
        : "+f"(d[0]), "+f"(d[1]), "+f"(d[2]), "+f"(d[3])
        : "r"(a[0]), "r"(a[1]), "r"(a[2]), "r"(a[3]), "r"(b0), "r"(b1));
}
__device__ __forceinline__ void split1(float x, unsigned short& h, unsigned short& l) {
    __nv_bfloat16 hb = __float2bfloat16(x);
    float r = x - __bfloat162float(hb);
    __nv_bfloat16 lb = __float2bfloat16(r);
    h = *reinterpret_cast<unsigned short*>(&hb);
    l = *reinterpret_cast<unsigned short*>(&lb);
}
__device__ __forceinline__ uint32_t pack_bf16x2(float lo, float hi) {
    uint32_t u;
    asm("cvt.rn.bf16x2.f32 %0, %1, %2;" : "=r"(u) : "f"(hi), "f"(lo));
    return u;
}

// ---------------------------------------------------------------------------
// conversion kernels (projections)
// ---------------------------------------------------------------------------
__global__ __launch_bounds__(256) void conv_split3(
    const float* __restrict__ X, __nv_bfloat16* __restrict__ Y, int n8)
{
    int i = blockIdx.x * 256 + threadIdx.x;
    if (i >= n8) return;
    float4 v0 = ((const float4*)X)[2 * i];
    float4 v1 = ((const float4*)X)[2 * i + 1];
    float e[8] = {v0.x, v0.y, v0.z, v0.w, v1.x, v1.y, v1.z, v1.w};
    union { unsigned short u[24]; uint4 q[3]; } o;
#pragma unroll
    for (int t = 0; t < 8; t++) {
        unsigned short h, l;
        split1(e[t], h, l);
        o.u[3 * t] = h; o.u[3 * t + 1] = h; o.u[3 * t + 2] = l;
    }
    uint4* dst = (uint4*)(Y + (size_t)i * 24);
    dst[0] = o.q[0]; dst[1] = o.q[1]; dst[2] = o.q[2];
}

__global__ __launch_bounds__(256) void conv_trans3(
    const float* __restrict__ W, __nv_bfloat16* __restrict__ W3, int K, int N)
{
    __shared__ float t[32][33];
    const int n0 = blockIdx.x * 32, k0 = blockIdx.y * 32;
    const int tx = threadIdx.x & 31, ty = threadIdx.x >> 5;
    for (int i = ty; i < 32; i += 8)
        t[i][tx] = W[(size_t)(k0 + i) * N + n0 + tx];
    __syncthreads();
    for (int i = ty; i < 32; i += 8) {
        unsigned short h, l;
        split1(t[tx][i], h, l);
        unsigned short* o = (unsigned short*)W3 + (size_t)(n0 + i) * (3 * K) + 3 * (k0 + tx);
        o[0] = h; o[1] = l; o[2] = h;
    }
}

// ---------------------------------------------------------------------------
// GEMM tiles / pipeline constants
// ---------------------------------------------------------------------------
#define BM 128
#define BN 256
#define BK 64
#define PIPE 3
#define A_BYTES (BM * BK * 2)
#define STAGE_BYTES (A_BYTES + BN * BK * 2)
#define GSMEM (PIPE * STAGE_BYTES)

// mainloop shared by both GEMM kernels (expects locals defined; see usage)
#define GEMM_MAINLOOP(NCvar)                                                      \
    issue(0);                                                                     \
    issue(1);                                                                     \
    for (int c = 0; c < (NCvar); c++) {                                           \
        if (c + 1 < (NCvar)) cp_wait<1>(); else cp_wait<0>();                     \
        __syncthreads();                                                          \
        if (c + 2 < (NCvar)) issue(c + 2);                                        \
        const int st = c % PIPE;                                                  \
        const uint32_t sA = sb + st * STAGE_BYTES;                                \
        const uint32_t sB = sA + A_BYTES;                                         \
        _Pragma("unroll")                                                         \
        for (int kf = 0; kf < 4; kf++) {                                          \
            uint32_t a[4][4], bfr[4][4];                                          \
            _Pragma("unroll")                                                     \
            for (int mf = 0; mf < 4; mf++) {                                      \
                uint32_t off = (uint32_t)(a_r + mf * 16) * 128 + kf * 32 + a_cb;  \
                uint32_t sw = off ^ ((off >> 3) & 0x70);                          \
                ldsm4(a[mf], sA + sw);                                            \
            }                                                                     \
            _Pragma("unroll")                                                     \
            for (int nf2 = 0; nf2 < 4; nf2++) {                                   \
                uint32_t off = (uint32_t)(b_r + nf2 * 16) * 128 + kf * 32 + b_cb; \
                uint32_t sw = off ^ ((off >> 3) & 0x70);                          \
                ldsm4(bfr[nf2], sB + sw);                                         \
            }                                                                     \
            _Pragma("unroll")                                                     \
            for (int mf = 0; mf < 4; mf++)                                        \
                _Pragma("unroll")                                                 \
                for (int nf2 = 0; nf2 < 4; nf2++) {                               \
                    mma16816(d[mf][2 * nf2],     a[mf], bfr[nf2][0], bfr[nf2][1]); \
                    mma16816(d[mf][2 * nf2 + 1], a[mf], bfr[nf2][2], bfr[nf2][3]); \
                }                                                                 \
    }

// ---------------------------------------------------------------------------
// Merged QKV projection GEMM. N = 8192 (Q 0..4095 | K 4096..6143 | V 6144..8191).
// Q/K parts -> g_QKV fp32; V part -> split-bf16 head-major planes directly.
// ---------------------------------------------------------------------------
__global__ __launch_bounds__(256, 1) void gemm_qkv(
    const __nv_bfloat16* __restrict__ A,
    const __nv_bfloat16* __restrict__ Bq,
    const __nv_bfloat16* __restrict__ Bk,
    const __nv_bfloat16* __restrict__ Bv)
{
    extern __shared__ char sm[];
    const uint32_t sb = smem_u32(sm);
    const int Kp = 3 * HIDDEN;
    const int tid = threadIdx.x;
    const int wid = tid >> 5, lane = tid & 31;
    const int wm = wid & 1, wn = wid >> 1;
    const int bm = blockIdx.y, bn = blockIdx.x;

    const __nv_bfloat16* Bsel;
    int bcol;
    if (bn < 16)      { Bsel = Bq; bcol = bn; }
    else if (bn < 24) { Bsel = Bk; bcol = bn - 16; }
    else              { Bsel = Bv; bcol = bn - 24; }

    const int arow[4] = {(tid + 0) >> 3, (tid + 256) >> 3, (tid + 512) >> 3, (tid + 768) >> 3};
    const int c16 = tid & 7;
    const uint32_t soff = ((uint32_t)c16 << 4);

    const __nv_bfloat16* Ag = A + (size_t)(bm * BM) * Kp + c16 * 8;
    const __nv_bfloat16* Bg = Bsel + (size_t)(bcol * BN) * Kp + c16 * 8;

    const int NC = Kp / BK;

    const int a_r = wm * 64 + (lane & 15);
    const uint32_t a_cb = ((uint32_t)(lane >> 4)) << 4;
    const int b_r = wn * 64 + ((lane >> 4) << 3) + (lane & 7);
    const uint32_t b_cb = ((uint32_t)((lane >> 3) & 1)) << 4;

    float d[4][8][4];
#pragma unroll
    for (int i = 0; i < 4; i++)
#pragma unroll
        for (int j = 0; j < 8; j++)
#pragma unroll
            for (int r = 0; r < 4; r++) d[i][j][r] = 0.f;

    auto issue = [&](int chunk) {
        const int st = chunk % PIPE;
        const uint32_t sA = sb + st * STAGE_BYTES;
        const uint32_t sB = sA + A_BYTES;
        const int k0 = chunk * BK;
#pragma unroll
        for (int j = 0; j < 4; j++) {
            const int row = arow[j];
            uint32_t off = ((uint32_t)row << 7) + soff;
            uint32_t sw = off ^ ((off >> 3) & 0x70);
            cp16(sA + sw, Ag + (size_t)row * Kp + k0);
        }
#pragma unroll
        for (int j = 0; j < 8; j++) {
            const int row = (tid + 256 * j) >> 3;
            uint32_t off = ((uint32_t)row << 7) + soff;
            uint32_t sw = off ^ ((off >> 3) & 0x70);
            cp16(sB + sw, Bg + (size_t)row * Kp + k0);
        }
        cp_commit();
    };

    GEMM_MAINLOOP(NC)
    }

    // ---- epilogue ----
    const int rloc = wm * 64 + (lane >> 2);
    const int cloc = wn * 64 + ((lane & 3) << 1);
    if (bn < 24) {
        // Q | K region -> fp32 g_QKV  (col = bn*256 + cloc + nf*8)
#pragma unroll
        for (int mf = 0; mf < 4; mf++) {
#pragma unroll
            for (int nf = 0; nf < 8; nf++) {
                const int r0 = bm * BM + rloc + mf * 16;
                const int c0 = bn * 256 + cloc + nf * 8;
                *(float2*)(g_QKV + (size_t)r0 * NQK + c0)       = make_float2(d[mf][nf][0], d[mf][nf][1]);
                *(float2*)(g_QKV + (size_t)(r0 + 8) * NQK + c0) = make_float2(d[mf][nf][2], d[mf][nf][3]);
            }
        }
    } else {
        // V region -> split-bf16 planes [b][kv][s][d]; kvh = bn - 24 (CTA-constant)
        const int kvh = bn - 24;
#pragma unroll
        for (int mf = 0; mf < 4; mf++) {
#pragma unroll
            for (int nf = 0; nf < 8; nf++) {
                const int r0 = bm * BM + rloc + mf * 16;
                const int d0 = cloc + nf * 8;
#pragma unroll
                for (int half = 0; half < 2; half++) {
                    const int r = r0 + 8 * half;
                    const int b = r >> 11, s = r & (SEQ - 1);
                    const size_t dst = ((size_t)(b * NKV + kvh) * SEQ + s) * DHEAD + d0;
                    unsigned short h0, l0, h1, l1;
                    split1(d[mf][nf][2 * half],     h0, l0);
                    split1(d[mf][nf][2 * half + 1], h1, l1);
                    *(ushort2*)((unsigned short*)g_Vh + dst) = make_ushort2(h0, h1);
                    *(ushort2*)((unsigned short*)g_Vl + dst) = make_ushort2(l0, l1);
                }
            }
        }
    }
}

// ---------------------------------------------------------------------------
// Generic GEMM (O-projection): C = A[M,Kp] @ B^T, fp32 out.
// ---------------------------------------------------------------------------
__global__ __launch_bounds__(256, 1) void gemm_bf16(
    const __nv_bfloat16* __restrict__ A, const __nv_bfloat16* __restrict__ B,
    float* __restrict__ C, int M, int N, int Kp)
{
    extern __shared__ char sm[];
    const uint32_t sb = smem_u32(sm);
    const int tid = threadIdx.x;
    const int wid = tid >> 5, lane = tid & 31;
    const int wm = wid & 1, wn = wid >> 1;
    const int bm = blockIdx.y, bn = blockIdx.x;

    const int arow[4] = {(tid + 0) >> 3, (tid + 256) >> 3, (tid + 512) >> 3, (tid + 768) >> 3};
    const int c16 = tid & 7;
    const uint32_t soff = ((uint32_t)c16 << 4);

    const __nv_bfloat16* Ag = A + (size_t)(bm * BM) * Kp + c16 * 8;
    const __nv_bfloat16* Bg = B + (size_t)(bn * BN) * Kp + c16 * 8;

    const int NC = Kp / BK;

    const int a_r = wm * 64 + (lane & 15);
    const uint32_t a_cb = ((uint32_t)(lane >> 4)) << 4;
    const int b_r = wn * 64 + ((lane >> 4) << 3) + (lane & 7);
    const uint32_t b_cb = ((uint32_t)((lane >> 3) & 1)) << 4;

    float d[4][8][4];
#pragma unroll
    for (int i = 0; i < 4; i++)
#pragma unroll
        for (int j = 0; j < 8; j++)
#pragma unroll
            for (int r = 0; r < 4; r++) d[i][j][r] = 0.f;

    auto issue = [&](int chunk) {
        const int st = chunk % PIPE;
        const uint32_t sA = sb + st * STAGE_BYTES;
        const uint32_t sB = sA + A_BYTES;
        const int k0 = chunk * BK;
#pragma unroll
        for (int j = 0; j < 4; j++) {
            const int row = arow[j];
            uint32_t off = ((uint32_t)row << 7) + soff;
            uint32_t sw = off ^ ((off >> 3) & 0x70);
            cp16(sA + sw, Ag + (size_t)row * Kp + k0);
        }
#pragma unroll
        for (int j = 0; j < 8; j++) {
            const int row = (tid + 256 * j) >> 3;
            uint32_t off = ((uint32_t)row << 7) + soff;
            uint32_t sw = off ^ ((off >> 3) & 0x70);
            cp16(sB + sw, Bg + (size_t)row * Kp + k0);
        }
        cp_commit();
    };

    GEMM_MAINLOOP(NC)
    }

    const int rbase = bm * BM + wm * 64 + (lane >> 2);
    const int cbase = bn * BN + wn * 64 + ((lane & 3) << 1);
#pragma unroll
    for (int mf = 0; mf < 4; mf++) {
#pragma unroll
        for (int nf = 0; nf < 8; nf++) {
            const int r0 = rbase + mf * 16;
            const int c0 = cbase + nf * 8;
            *(float2*)(C + (size_t)r0 * N + c0)       = make_float2(d[mf][nf][0], d[mf][nf][1]);
            *(float2*)(C + (size_t)(r0 + 8) * N + c0) = make_float2(d[mf][nf][2], d[mf][nf][3]);
        }
    }
}

// ---------------------------------------------------------------------------
// Fused per-head RMSNorm + RoPE (+ q scale), reading g_QKV, writing split planes.
// ---------------------------------------------------------------------------
__global__ __launch_bounds__(256) void norm_rope_split(
    const float* __restrict__ cosT, const float* __restrict__ sinT,
    const float* __restrict__ qw, const float* __restrict__ kw)
{
    const int row  = blockIdx.x;
    const int head = blockIdx.y;
    const int d    = threadIdx.x;
    const int b    = row >> 11;
    const int s    = row & (SEQ - 1);

    const float* src;
    const float* w;
    const bool isq = head < NHEAD;
    if (isq) { src = g_QKV + (size_t)row * NQK + head * DHEAD;              w = qw; }
    else     { src = g_QKV + (size_t)row * NQK + QD + (head - NHEAD) * DHEAD; w = kw; }

    float x = src[d];
    __shared__ float red[8];
    __shared__ float nsh[256];
    float v = x * x;
#pragma unroll
    for (int o = 16; o > 0; o >>= 1) v += __shfl_xor_sync(0xffffffffu, v, o);
    if ((d & 31) == 0) red[d >> 5] = v;
    __syncthreads();
    if (d == 0) {
        float t = 0.f;
#pragma unroll
        for (int i = 0; i < 8; i++) t += red[i];
        red[0] = t;
    }
    __syncthreads();
    const float rms = rsqrtf(red[0] * (1.f / 256.f) + 1e-6f);
    const float n   = x * rms * (1.f + w[d]);
    nsh[d] = n;
    __syncthreads();
    const int i  = d & 127;
    const float c  = cosT[s * 128 + i];
    const float sn = sinT[s * 128 + i];
    float o = (d < 128) ? (n * c - nsh[d + 128] * sn)
                        : (nsh[d - 128] * sn + n * c);
    if (isq) o *= 0.0625f;

    __nv_bfloat16 hb = __float2bfloat16(o);
    __nv_bfloat16 lb = __float2bfloat16(o - __bfloat162float(hb));
    if (isq) {
        const size_t dst = ((size_t)(b * NHEAD + head) * SEQ + s) * DHEAD + d;
        g_Qh[dst] = hb; g_Ql[dst] = lb;
    } else {
        const size_t dst = ((size_t)(b * NKV + head - NHEAD) * SEQ + s) * DHEAD + d;
        g_Kh[dst] = hb; g_Kl[dst] = lb;
    }
}

// ---------------------------------------------------------------------------
// Tensor-core flash attention, triple-bf16 split, causal.
// Epilogue writes triple-interleaved Ao3 directly.
// ---------------------------------------------------------------------------
#define SQH 0
#define SQL 65536
#define SKH 131072
#define SKL (131072 + 16384)
#define SVH (131072 + 32768)
#define SVL (131072 + 49152)
#define ATT_SMEM (131072 + 65536)   // 196608 bytes

__global__ __launch_bounds__(256, 1) void attn_mma()
{
    extern __shared__ char sm[];
    const uint32_t sb = smem_u32(sm);
    const int tid = threadIdx.x, lane = tid & 31, w = tid >> 5;
    const int qt  = gridDim.x - 1 - blockIdx.x;
    const int bh  = blockIdx.y;
    const int b = bh >> 4, h = bh & 15, kvh = h >> 1;
    const int q0 = qt * 128;

    const char* Qhg = (const char*)(g_Qh + ((size_t)(b * NHEAD + h) * SEQ + q0) * DHEAD);
    const char* Qlg = (const char*)(g_Ql + ((size_t)(b * NHEAD + h) * SEQ + q0) * DHEAD);
    const char* Khg = (const char*)(g_Kh + (size_t)(b * NKV + kvh) * SEQ * DHEAD);
    const char* Klg = (const char*)(g_Kl + (size_t)(b * NKV + kvh) * SEQ * DHEAD);
    const char* Vhg = (const char*)(g_Vh + (size_t)(b * NKV + kvh) * SEQ * DHEAD);
    const char* Vlg = (const char*)(g_Vl + (size_t)(b * NKV + kvh) * SEQ * DHEAD);

#pragma unroll
    for (int i = 0; i < 16; i++) {
        const int id = tid + 256 * i, r = id >> 5, c = id & 31;
        const uint32_t sw = (uint32_t)(r * 512) + (uint32_t)((c ^ (r & 7)) << 4);
        cp16(sb + SQH + sw, Qhg + r * 512 + c * 16);
        cp16(sb + SQL + sw, Qlg + r * 512 + c * 16);
    }
    cp_commit();

    const int a_row   = w * 16 + (lane & 15);
    const int a_coff  = lane >> 4;
    const uint32_t aqh = sb + SQH + a_row * 512;
    const uint32_t aql = sb + SQL + a_row * 512;
    const int kb_row  = (lane & 7) + 8 * (lane >> 4);
    const int kb_coff = (lane >> 3) & 1;
    const int vb_row  = (lane & 7) + 8 * ((lane >> 3) & 1);
    const int vb_coff = lane >> 4;
    const int gr  = lane >> 2;
    const int gc2 = 2 * (lane & 3);

    float acc[32][4];
#pragma unroll
    for (int n = 0; n < 32; n++) {
        acc[n][0] = 0.f; acc[n][1] = 0.f; acc[n][2] = 0.f; acc[n][3] = 0.f;
    }
    float m0 = -INFINITY, m1 = -INFINITY, l0 = 0.f, l1 = 0.f;

    cp_wait<0>();
    __syncthreads();

    const int ntiles = 4 * qt + 4;
    for (int kt = 0; kt < ntiles; kt++) {
        const int k0 = kt * 32;
        __syncthreads();
#pragma unroll
        for (int i = 0; i < 4; i++) {
            const int id = tid + 256 * i, r = id >> 5, c = id & 31;
            const uint32_t sw = (uint32_t)(r * 512) + (uint32_t)((c ^ (r & 7)) << 4);
            const size_t go = (size_t)(k0 + r) * 512 + c * 16;
            cp16(sb + SKH + sw, Khg + go);
            cp16(sb + SKL + sw, Klg + go);
        }
        cp_commit();
#pragma unroll
        for (int i = 0; i < 4; i++) {
            const int id = tid + 256 * i, r = id >> 5, c = id & 31;
            const uint32_t sw = (uint32_t)(r * 512) + (uint32_t)((c ^ (r & 7)) << 4);
            const size_t go = (size_t)(k0 + r) * 512 + c * 16;
            cp16(sb + SVH + sw, Vhg + go);
            cp16(sb + SVL + sw, Vlg + go);
        }
        cp_commit();
        cp_wait<1>();
        __syncthreads();

        float s4[4][4];
#pragma unroll
        for (int t = 0; t < 4; t++) { s4[t][0]=0.f; s4[t][1]=0.f; s4[t][2]=0.f; s4[t][3]=0.f; }
#pragma unroll
        for (int k = 0; k < 16; k++) {
            uint32_t ah[4], al[4];
            const uint32_t ca = (uint32_t)(2 * k + a_coff);
            const uint32_t aoff = ((ca ^ (uint32_t)(a_row & 7)) << 4);
            ldsm4(ah, aqh + aoff);
            ldsm4(al, aql + aoff);
#pragma unroll
            for (int p = 0; p < 2; p++) {
                const int row = 16 * p + kb_row;
                const uint32_t ck = (uint32_t)(2 * k + kb_coff);
                const uint32_t koff = (uint32_t)(row * 512) + ((ck ^ (uint32_t)(row & 7)) << 4);
                uint32_t kh4[4], kl4[4];
                ldsm4(kh4, sb + SKH + koff);
                ldsm4(kl4, sb + SKL + koff);
                mma16816(s4[2*p],   ah, kh4[0], kh4[1]);
                mma16816(s4[2*p],   ah, kl4[0], kl4[1]);
                mma16816(s4[2*p],   al, kh4[0], kh4[1]);
                mma16816(s4[2*p+1], ah, kh4[2], kh4[3]);
                mma16816(s4[2*p+1], ah, kl4[2], kl4[3]);
                mma16816(s4[2*p+1], al, kh4[2], kh4[3]);
            }
        }

        if (kt >= 4 * qt) {
            const int qrow0 = q0 + w * 16 + gr;
#pragma unroll
            for (int t = 0; t < 4; t++) {
                const int kvc = k0 + 8 * t + gc2;
                if (kvc     > qrow0)     s4[t][0] = -1e9f;
                if (kvc + 1 > qrow0)     s4[t][1] = -1e9f;
                if (kvc     > qrow0 + 8) s4[t][2] = -1e9f;
                if (kvc + 1 > qrow0 + 8) s4[t][3] = -1e9f;
            }
        }

        float mx0 = -INFINITY, mx1 = -INFINITY;
#pragma unroll
        for (int t = 0; t < 4; t++) {
            mx0 = fmaxf(mx0, fmaxf(s4[t][0], s4[t][1]));
            mx1 = fmaxf(mx1, fmaxf(s4[t][2], s4[t][3]));
        }
        mx0 = fmaxf(mx0, __shfl_xor_sync(0xffffffffu, mx0, 1));
        mx0 = fmaxf(mx0, __shfl_xor_sync(0xffffffffu, mx0, 2));
        mx1 = fmaxf(mx1, __shfl_xor_sync(0xffffffffu, mx1, 1));
        mx1 = fmaxf(mx1, __shfl_xor_sync(0xffffffffu, mx1, 2));
        const float nm0 = fmaxf(m0, mx0), nm1 = fmaxf(m1, mx1);
        const float f0 = __expf(m0 - nm0), f1 = __expf(m1 - nm1);
        m0 = nm0; m1 = nm1;

        float ps0 = 0.f, ps1 = 0.f;
        uint32_t ph[4][2], pl[4][2];
#pragma unroll
        for (int t = 0; t < 4; t++) {
            const float p0 = __expf(s4[t][0] - nm0);
            const float p1 = __expf(s4[t][1] - nm0);
            const float p2 = __expf(s4[t][2] - nm1);
            const float p3 = __expf(s4[t][3] - nm1);
            ps0 += p0 + p1; ps1 += p2 + p3;
            const uint32_t h01 = pack_bf16x2(p0, p1);
            const uint32_t h23 = pack_bf16x2(p2, p3);
            const float r0 = p0 - __uint_as_float(h01 << 16);
            const float r1 = p1 - __uint_as_float(h01 & 0xffff0000u);
            const float r2 = p2 - __uint_as_float(h23 << 16);
            const float r3 = p3 - __uint_as_float(h23 & 0xffff0000u);
            ph[t][0] = h01; ph[t][1] = h23;
            pl[t][0] = pack_bf16x2(r0, r1);
            pl[t][1] = pack_bf16x2(r2, r3);
        }
        ps0 += __shfl_xor_sync(0xffffffffu, ps0, 1);
        ps0 += __shfl_xor_sync(0xffffffffu, ps0, 2);
        ps1 += __shfl_xor_sync(0xffffffffu, ps1, 1);
        ps1 += __shfl_xor_sync(0xffffffffu, ps1, 2);
        l0 = l0 * f0 + ps0;
        l1 = l1 * f1 + ps1;
#pragma unroll
        for (int n = 0; n < 32; n++) {
            acc[n][0] *= f0; acc[n][1] *= f0; acc[n][2] *= f1; acc[n][3] *= f1;
        }

        cp_wait<0>();
        __syncthreads();

#pragma unroll
        for (int j = 0; j < 2; j++) {
            uint32_t ah[4] = {ph[2*j][0], ph[2*j][1], ph[2*j+1][0], ph[2*j+1][1]};
            uint32_t al[4] = {pl[2*j][0], pl[2*j][1], pl[2*j+1][0], pl[2*j+1][1]};
            const int row = 16 * j + vb_row;
            const uint32_t vbase = (uint32_t)(row * 512);
            const uint32_t rx = (uint32_t)(row & 7);
#pragma unroll
            for (int np = 0; np < 16; np++) {
                const uint32_t c = (uint32_t)(2 * np + vb_coff);
                const uint32_t voff = vbase + ((c ^ rx) << 4);
                uint32_t vh4[4], vl4[4];
                ldsm4t(vh4, sb + SVH + voff);
                ldsm4t(vl4, sb + SVL + voff);
                mma16816(acc[2*np],   ah, vh4[0], vh4[1]);
                mma16816(acc[2*np],   ah, vl4[0], vl4[1]);
                mma16816(acc[2*np],   al, vh4[0], vh4[1]);
                mma16816(acc[2*np+1], ah, vh4[2], vh4[3]);
                mma16816(acc[2*np+1], ah, vl4[2], vl4[3]);
                mma16816(acc[2*np+1], al, vh4[2], vh4[3]);
            }
        }
    }

    // epilogue: write triple-interleaved Ao3 directly
    const float i0 = 1.f / l0, i1 = 1.f / l1;
    const int r0g = q0 + w * 16 + gr;
#pragma unroll
    for (int n = 0; n < 32; n++) {
#pragma unroll
        for (int half = 0; half < 2; half++) {
            const int row = r0g + 8 * half;
            const int col = h * DHEAD + 8 * n + gc2;
            const float inv = half ? i1 : i0;
            const float v0 = acc[n][2 * half]     * inv;
            const float v1 = acc[n][2 * half + 1] * inv;
            unsigned short h0, l0v, h1, l1v;
            split1(v0, h0, l0v);
            split1(v1, h1, l1v);
            uint32_t* dst = (uint32_t*)((unsigned short*)g_Ao3 +
                              ((size_t)(b * SEQ) + row) * (3 * QD) + 3 * col);
            dst[0] = (uint32_t)h0 | ((uint32_t)h0 << 16);
            dst[1] = (uint32_t)l0v | ((uint32_t)h1 << 16);
            dst[2] = (uint32_t)h1 | ((uint32_t)l1v << 16);
        }
    }
}

// ---------------------------------------------------------------------------
extern "C" void kernel_launch(void* const* d_in, const int* in_sizes, int n_in,
                              void* d_out, int out_size)
{
    const float* hidden = (const float*)d_in[0];
    const float* cosT   = (const float*)d_in[1];
    const float* sinT   = (const float*)d_in[2];
    const float* qw     = (const float*)d_in[4];
    const float* kw     = (const float*)d_in[5];
    const float* vw     = (const float*)d_in[6];
    const float* ow     = (const float*)d_in[7];
    const float* qnw    = (const float*)d_in[8];
    const float* knw    = (const float*)d_in[9];
    float* out = (float*)d_out;

    __nv_bfloat16 *X3, *Ao3, *Wq3, *Wk3, *Wv3, *Wo3;
    cudaGetSymbolAddress((void**)&X3, g_X3);
    cudaGetSymbolAddress((void**)&Ao3, g_Ao3);
    cudaGetSymbolAddress((void**)&Wq3, g_Wq3);
    cudaGetSymbolAddress((void**)&Wk3, g_Wk3);
    cudaGetSymbolAddress((void**)&Wv3, g_Wv3);
    cudaGetSymbolAddress((void**)&Wo3, g_Wo3);

    cudaFuncSetAttribute(gemm_qkv,  cudaFuncAttributeMaxDynamicSharedMemorySize, GSMEM);
    cudaFuncSetAttribute(gemm_bf16, cudaFuncAttributeMaxDynamicSharedMemorySize, GSMEM);
    cudaFuncSetAttribute(attn_mma,  cudaFuncAttributeMaxDynamicSharedMemorySize, ATT_SMEM);

    dim3 blk(256);
    // convert activations + weights to triple-interleaved split bf16
    conv_split3<<<(NROW * HIDDEN / 8 + 255) / 256, blk>>>(hidden, X3, NROW * HIDDEN / 8);
    conv_trans3<<<dim3(QD / 32, HIDDEN / 32), blk>>>(qw, Wq3, HIDDEN, QD);
    conv_trans3<<<dim3(KD / 32, HIDDEN / 32), blk>>>(kw, Wk3, HIDDEN, KD);
    conv_trans3<<<dim3(KD / 32, HIDDEN / 32), blk>>>(vw, Wv3, HIDDEN, KD);
    conv_trans3<<<dim3(HIDDEN / 32, QD / 32), blk>>>(ow, Wo3, QD, HIDDEN);

    // Merged QKV projection (one launch; V written as split planes directly)
    gemm_qkv<<<dim3(32, NROW / BM), blk, GSMEM>>>(X3, Wq3, Wk3, Wv3);

    // RMSNorm + RoPE -> head-major split-bf16 planes
    norm_rope_split<<<dim3(NROW, NHEAD + NKV), blk>>>(cosT, sinT, qnw, knw);

    // Tensor-core flash attention (writes Ao3 triple directly)
    attn_mma<<<dim3(SEQ / 128, B_SZ * NHEAD), blk, ATT_SMEM>>>();

    // Output projection
    gemm_bf16<<<dim3(HIDDEN / BN, NROW / BM), blk, GSMEM>>>(Ao3, Wo3, out, NROW, HIDDEN, 3 * QD);
}